// round 9
// baseline (speedup 1.0000x reference)
#include <cuda_runtime.h>
#include <cstdint>

#define NB   8
#define CIN  64
#define COUT 128
#define HH   32
#define WW   32
#define QWN  (COUT*144)            // 18432 int32 words of packed B

#define BOFF   0
#define BROW   592                 // 576+16 pad (37*16B, odd) -> conflict-free ldmatrix
#define BSZ    (COUT*BROW)         // 75776
#define STAG   BSZ                 // staging: 4 rows x 34 cols x 80B/pixel
#define PIXSTR 80                  // 16B chunks at 80B stride hit all 32 banks in ldmatrix
#define STSZ   (4*34*PIXSTR)       // 10880
#define MRG    (STAG + STSZ)       // 86656: K-split merge buffer 8 warps x 32 lanes x 32 regs
#define MRGSZ  (8*32*32*4)         // 32768
#define SMEM_SZ (MRG + MRGSZ)      // 119424

#define NCTA 128
#define NTHR 512

// ---------------- scratch (device globals; no allocation) ----------------
__device__ unsigned g_partx[NCTA];
__device__ unsigned g_partw[NCTA];
__device__ int      g_wpack[QWN];         // [co][k] row-major, 576B per co
__device__ unsigned g_barA = 0u;          // monotonic grid-barrier counters
__device__ unsigned g_barB = 0u;

__device__ __forceinline__ uint32_t smem_u32(const void* p) {
    uint32_t a;
    asm("{ .reg .u64 t; cvta.to.shared.u64 t, %1; cvt.u32.u64 %0, t; }" : "=r"(a) : "l"(p));
    return a;
}

#define LDSM_X4(r0, r1, r2, r3, a) \
    asm volatile("ldmatrix.sync.aligned.m8n8.x4.shared.b16 {%0,%1,%2,%3}, [%4];" \
                 : "=r"(r0), "=r"(r1), "=r"(r2), "=r"(r3) : "r"(a))

#define IMMA(c, a0, a1, a2, a3, b0, b1) \
    asm volatile("mma.sync.aligned.m16n8k32.row.col.s32.s8.s8.s32 " \
                 "{%0,%1,%2,%3}, {%4,%5,%6,%7}, {%8,%9}, {%0,%1,%2,%3};" \
                 : "+r"((c)[0]), "+r"((c)[1]), "+r"((c)[2]), "+r"((c)[3]) \
                 : "r"(a0), "r"(a1), "r"(a2), "r"(a3), "r"(b0), "r"(b1))

__device__ __forceinline__ unsigned umax4(float4 v) {
    unsigned m = __float_as_uint(fabsf(v.x));
    m = max(m, __float_as_uint(fabsf(v.y)));
    m = max(m, __float_as_uint(fabsf(v.z)));
    m = max(m, __float_as_uint(fabsf(v.w)));
    return m;
}

__device__ __forceinline__ int quant(float v, float s) {
    float r = rintf(__fmul_rn(v, s));      // round half-to-even == jnp.round
    r = fminf(fmaxf(r, -128.0f), 127.0f);
    return (int)r;
}

// software grid barrier: all 128 CTAs co-resident (grid < #SMs), monotonic counter
__device__ __forceinline__ void grid_bar(unsigned* bar) {
    __syncthreads();
    if (threadIdx.x == 0) {
        __threadfence();
        unsigned ticket = atomicAdd(bar, 1u);
        unsigned target = (ticket & ~127u) + 128u;
        while ((int)(atomicAdd(bar, 0u) - target) < 0) { }
    }
    __syncthreads();
}

// K-half mainloop: KH=0 -> ksteps 0..8, KH=1 -> 9..17 (compile-time tap offsets)
template<int KH>
__device__ __forceinline__ void mainloop(uint32_t aAddr0, const uint32_t* bAddr, int acc[8][4]) {
    #pragma unroll
    for (int j = 0; j < 9; ++j) {
        const int ks  = KH*9 + j;
        const int tap = ks >> 1;
        const uint32_t aoff = (uint32_t)(((tap/3)*34 + (tap%3))*PIXSTR + (ks & 1)*32);
        const uint32_t boff = (uint32_t)ks * 32;
        uint32_t a[4], bb[4][4];
        LDSM_X4(a[0], a[1], a[2], a[3], aAddr0 + aoff);
        #pragma unroll
        for (int np = 0; np < 4; ++np)
            LDSM_X4(bb[np][0], bb[np][1], bb[np][2], bb[np][3], bAddr[np] + boff);
        #pragma unroll
        for (int nf = 0; nf < 8; ++nf)
            IMMA(acc[nf], a[0], a[1], a[2], a[3],
                 bb[nf >> 1][(nf & 1)*2], bb[nf >> 1][(nf & 1)*2 + 1]);
    }
}

// ---------------- ONE fused kernel ----------------
__global__ void __launch_bounds__(NTHR, 1)
k_fused(const float* __restrict__ x, const float* __restrict__ w,
        const float* __restrict__ bias,
        const float* __restrict__ Tf_in, const float* __restrict__ Tw_in,
        float* __restrict__ out) {
    extern __shared__ char sm[];
    __shared__ unsigned sredx[16], sredw[16];
    __shared__ float s_sc[3];

    const int t = threadIdx.x, wid = t >> 5, lane = t & 31;
    const int g = blockIdx.x*NTHR + t;        // 0..65535
    const int b  = blockIdx.x >> 4;
    const int y0 = (blockIdx.x & 15) * 2;

    // ===== phase 1: grid-wide |max| reduce =====
    {
        const float4* x4 = (const float4*)x;
        const float4* w4 = (const float4*)w;
        unsigned mx = max(umax4(x4[g]), umax4(x4[g + 65536]));
        unsigned mw = (g < QWN) ? umax4(w4[g]) : 0u;
        #pragma unroll
        for (int o = 16; o; o >>= 1) {
            mx = max(mx, __shfl_xor_sync(0xffffffffu, mx, o));
            mw = max(mw, __shfl_xor_sync(0xffffffffu, mw, o));
        }
        if (lane == 0) { sredx[wid] = mx; sredw[wid] = mw; }
        __syncthreads();
        if (t < 32) {
            mx = (t < 16) ? sredx[t] : 0u;
            mw = (t < 16) ? sredw[t] : 0u;
            #pragma unroll
            for (int o = 8; o; o >>= 1) {
                mx = max(mx, __shfl_xor_sync(0xffffffffu, mx, o));
                mw = max(mw, __shfl_xor_sync(0xffffffffu, mw, o));
            }
            if (t == 0) { g_partx[blockIdx.x] = mx; g_partw[blockIdx.x] = mw; }
        }
    }
    grid_bar(&g_barA);

    // ===== phase 2: every CTA finalizes scales locally =====
    {
        unsigned vx = (t < NCTA) ? g_partx[t] : 0u;
        unsigned vw = (t < NCTA) ? g_partw[t] : 0u;
        #pragma unroll
        for (int o = 16; o; o >>= 1) {
            vx = max(vx, __shfl_xor_sync(0xffffffffu, vx, o));
            vw = max(vw, __shfl_xor_sync(0xffffffffu, vw, o));
        }
        if (lane == 0 && t < NCTA) { sredx[wid] = vx; sredw[wid] = vw; }
        __syncthreads();
        if (t == 0) {
            unsigned mx = 0u, mw = 0u;
            #pragma unroll
            for (int i = 0; i < 4; ++i) { mx = max(mx, sredx[i]); mw = max(mw, sredw[i]); }
            float Tf = __fadd_rn(__fmul_rn(0.95f, Tf_in[0]), __fmul_rn(0.05f, __uint_as_float(mx)));
            float Tw = __fadd_rn(__fmul_rn(0.95f, Tw_in[0]), __fmul_rn(0.05f, __uint_as_float(mw)));
            s_sc[0] = __fdiv_rn(127.0f, Tf);
            s_sc[1] = __fdiv_rn(127.0f, Tw);
            s_sc[2] = __fmul_rn(__fdiv_rn(Tf, 127.0f), __fdiv_rn(Tw, 127.0f));
        }
        __syncthreads();
    }

    // ===== phase 3a: quantize OWN x halo into smem staging (local, no global pack) =====
    for (int i = t; i < 4*34*4; i += NTHR) {
        int c4 = i & 3;
        int s  = i >> 2;                      // sr*34 + sc
        int sc = s % 34, sr = s / 34;
        int R  = y0 + sr;                     // padded row
        int4 v = make_int4(0, 0, 0, 0);
        if (R >= 1 && R <= HH && sc >= 1 && sc <= WW) {
            const float sf = s_sc[0];
            const float* px = x + (((b*CIN + c4*16)*HH) + (R - 1))*WW + (sc - 1);
            int q[16];
            #pragma unroll
            for (int j = 0; j < 16; ++j)
                q[j] = quant(px[j*HH*WW], sf) & 255;
            v.x = q[0]  | (q[1]  << 8) | (q[2]  << 16) | (q[3]  << 24);
            v.y = q[4]  | (q[5]  << 8) | (q[6]  << 16) | (q[7]  << 24);
            v.z = q[8]  | (q[9]  << 8) | (q[10] << 16) | (q[11] << 24);
            v.w = q[12] | (q[13] << 8) | (q[14] << 16) | (q[15] << 24);
        }
        *(int4*)(sm + STAG + s*PIXSTR + c4*16) = v;
    }

    // ===== phase 3b: quantize+pack weights to global (144 items per CTA) =====
    if (t < 144) {
        const int i = blockIdx.x*144 + t;     // 0..18431: [co][tap][chunk]
        const int co  = i / 144;
        const int rem = i % 144;
        const int tap = rem >> 4;
        const int c4w = rem & 15;
        const float sf = s_sc[1];
        const float* pw = w + (co*CIN + c4w*4)*9 + tap;
        int q0 = quant(pw[0],  sf) & 255;
        int q1 = quant(pw[9],  sf) & 255;
        int q2 = quant(pw[18], sf) & 255;
        int q3 = quant(pw[27], sf) & 255;
        g_wpack[i] = q0 | (q1 << 8) | (q2 << 16) | (q3 << 24);
    }
    grid_bar(&g_barB);

    // ===== phase 4: fill B smem [co][576B] stride 592 (4608 int4) =====
    {
        const int4* __restrict__ src = (const int4*)g_wpack;
        int4* __restrict__ Bm = (int4*)(sm + BOFF);
        #pragma unroll
        for (int k = 0; k < 9; ++k) {
            int i = t + k*NTHR;
            int co = i / 36, j = i % 36;
            Bm[co*37 + j] = src[i];
        }
    }
    __syncthreads();

    // ===== phase 5: IMMA mainloop; 16 warps = 4(M) x 2(N=64) x 2(K-halves) =====
    const int m  = wid & 3;
    const int n  = (wid >> 2) & 1;
    const int kh = wid >> 3;
    const int wm = m * 16;
    const int wn = n * 64;
    const uint32_t sbase = smem_u32(sm);

    // A via per-lane ldmatrix addresses straight into staging (im2col = address math)
    const int pix = wm + (lane & 15);
    const uint32_t aAddr0 = sbase + STAG
                          + (uint32_t)(((pix >> 5)*34 + (pix & 31))*PIXSTR)
                          + (uint32_t)(lane >> 4)*16;
    uint32_t bAddr[4];
    #pragma unroll
    for (int np = 0; np < 4; ++np)
        bAddr[np] = sbase + BOFF
                  + (uint32_t)(wn + np*16 + (lane & 7) + ((lane >> 4) & 1)*8)*BROW
                  + (uint32_t)((lane >> 3) & 1)*16;

    int acc[8][4];
    #pragma unroll
    for (int nf = 0; nf < 8; ++nf)
        #pragma unroll
        for (int j = 0; j < 4; ++j) acc[nf][j] = 0;

    if (kh == 0) mainloop<0>(aAddr0, bAddr, acc);
    else         mainloop<1>(aAddr0, bAddr, acc);

    // ===== phase 6: merge K-halves (exact s32 add via smem) =====
    const int q = m*2 + n;                    // 0..7
    if (kh == 1) {
        #pragma unroll
        for (int nf = 0; nf < 8; ++nf)
            *(int4*)(sm + MRG + ((q*8 + nf)*32 + lane)*16) =
                make_int4(acc[nf][0], acc[nf][1], acc[nf][2], acc[nf][3]);
    }
    __syncthreads();

    if (kh == 0) {
        #pragma unroll
        for (int nf = 0; nf < 8; ++nf) {
            int4 o4 = *(const int4*)(sm + MRG + ((q*8 + nf)*32 + lane)*16);
            acc[nf][0] += o4.x; acc[nf][1] += o4.y; acc[nf][2] += o4.z; acc[nf][3] += o4.w;
        }
        // ===== epilogue: s32 -> f32 * sc + bias =====
        const float sc = s_sc[2];
        const int p0 = wm + (lane >> 2);
        #pragma unroll
        for (int nf = 0; nf < 8; ++nf) {
            const int co0 = wn + nf*8 + (lane & 3)*2;
            const float b0 = __ldg(&bias[co0]);
            const float b1 = __ldg(&bias[co0 + 1]);
            #pragma unroll
            for (int half = 0; half < 2; ++half) {
                const int p = p0 + half*8;
                const int y = y0 + (p >> 5), xx = p & 31;
                float* po = out + (((size_t)b*COUT + co0)*HH + y)*WW + xx;
                po[0]     = (float)acc[nf][half*2]     * sc + b0;
                po[HH*WW] = (float)acc[nf][half*2 + 1] * sc + b1;
            }
        }
    }
}

// ---------------- launch ----------------
extern "C" void kernel_launch(void* const* d_in, const int* in_sizes, int n_in,
                              void* d_out, int out_size) {
    const float* x    = (const float*)d_in[0];
    const float* w    = (const float*)d_in[1];
    const float* bias = (const float*)d_in[2];
    // d_in[3] = lut (exact a*b -> tensor core), d_in[4] = gradient_lut (unused)
    const float* Tf   = (const float*)d_in[5];
    const float* Tw   = (const float*)d_in[6];
    float* out = (float*)d_out;

    cudaFuncSetAttribute(k_fused, cudaFuncAttributeMaxDynamicSharedMemorySize, SMEM_SZ);
    k_fused<<<NCTA, NTHR, SMEM_SZ>>>(x, w, bias, Tf, Tw, out);
}

// round 10
// speedup vs baseline: 1.0611x; 1.0611x over previous
#include <cuda_runtime.h>
#include <cstdint>

#define NB   8
#define CIN  64
#define COUT 128
#define HH   32
#define WW   32
#define QWN  (COUT*144)            // 18432 int32 words of packed B

#define BOFF   0
#define BROW   592                 // 576+16 pad (37*16B, odd) -> conflict-free ldmatrix
#define BSZ    (COUT*BROW)         // 75776
#define HALO   BSZ                 // float halo: 136 pixels x 65 floats (pad) = 35360 B
#define HSTR   65
#define STAGE  (HALO + 136*HSTR*4) // 111136: int8 staging, 136 pixels x 80 B
#define PIXSTR 80
#define WROW   (STAGE + 136*PIXSTR)// 122016: w-row floats (576)
#define SMEM_SZ (WROW + 576*4)     // 124320

#define NCTA 128
#define NTHR 512

// ---------------- scratch (device globals; no allocation) ----------------
__device__ unsigned g_partx[NCTA];
__device__ unsigned g_partw[NCTA];
__device__ int      g_wpack[QWN];         // [co][tap][c4w] = co*144 + tap*16 + c4w
__device__ unsigned g_barA = 0u;          // monotonic grid-barrier counters
__device__ unsigned g_barB = 0u;

__device__ __forceinline__ uint32_t smem_u32(const void* p) {
    uint32_t a;
    asm("{ .reg .u64 t; cvta.to.shared.u64 t, %1; cvt.u32.u64 %0, t; }" : "=r"(a) : "l"(p));
    return a;
}

#define LDSM_X4(r0, r1, r2, r3, a) \
    asm volatile("ldmatrix.sync.aligned.m8n8.x4.shared.b16 {%0,%1,%2,%3}, [%4];" \
                 : "=r"(r0), "=r"(r1), "=r"(r2), "=r"(r3) : "r"(a))

#define IMMA(c, a0, a1, a2, a3, b0, b1) \
    asm volatile("mma.sync.aligned.m16n8k32.row.col.s32.s8.s8.s32 " \
                 "{%0,%1,%2,%3}, {%4,%5,%6,%7}, {%8,%9}, {%0,%1,%2,%3};" \
                 : "+r"((c)[0]), "+r"((c)[1]), "+r"((c)[2]), "+r"((c)[3]) \
                 : "r"(a0), "r"(a1), "r"(a2), "r"(a3), "r"(b0), "r"(b1))

__device__ __forceinline__ int quant(float v, float s) {
    float r = rintf(__fmul_rn(v, s));      // round half-to-even == jnp.round
    r = fminf(fmaxf(r, -128.0f), 127.0f);
    return (int)r;
}

// grid barrier: all 128 CTAs co-resident (grid < #SMs); monotonic counter,
// arrival = atomicAdd (release via prior fence), poll = ld.acquire (no RMW serialization)
__device__ __forceinline__ void grid_bar(unsigned* bar) {
    __syncthreads();
    if (threadIdx.x == 0) {
        __threadfence();
        unsigned ticket = atomicAdd(bar, 1u);
        unsigned target = (ticket & ~127u) + 128u;
        unsigned v;
        do {
            asm volatile("ld.acquire.gpu.u32 %0, [%1];" : "=r"(v) : "l"(bar) : "memory");
        } while ((int)(v - target) < 0);
    }
    __syncthreads();
}

// ---------------- ONE fused kernel ----------------
__global__ void __launch_bounds__(NTHR, 1)
k_fused(const float* __restrict__ x, const float* __restrict__ w,
        const float* __restrict__ bias,
        const float* __restrict__ Tf_in, const float* __restrict__ Tw_in,
        float* __restrict__ out) {
    extern __shared__ char sm[];
    __shared__ unsigned sredx[16], sredw[16];
    __shared__ float s_sc[3];

    const int t = threadIdx.x, wid = t >> 5, lane = t & 31;
    const int b  = blockIdx.x >> 4;
    const int y0 = (blockIdx.x & 15) * 2;

    float* __restrict__ halo = (float*)(sm + HALO);
    float* __restrict__ wrow = (float*)(sm + WROW);

    // ===== phase 1: load OWN float halo + w row into smem, local |max| =====
    unsigned mx = 0u, mw = 0u;
    {
        #pragma unroll
        for (int k = 0; k < 17; ++k) {         // 17*512 = 8704 = 136 pix * 64 ch exactly
            int i = t + k*NTHR;
            int pix = i % 136, ch = i / 136;
            int sc = pix % 34, sr = pix / 34;
            int R  = y0 + sr;                   // padded row
            float v = 0.0f;
            if (R >= 1 && R <= HH && sc >= 1 && sc <= WW)
                v = x[((b*CIN + ch)*HH + (R - 1))*WW + (sc - 1)];
            halo[pix*HSTR + ch] = v;
            mx = max(mx, __float_as_uint(fabsf(v)));
        }
        float wv = w[blockIdx.x*576 + t];
        wrow[t] = wv;
        mw = __float_as_uint(fabsf(wv));
        if (t < 64) {
            float wv2 = w[blockIdx.x*576 + 512 + t];
            wrow[512 + t] = wv2;
            mw = max(mw, __float_as_uint(fabsf(wv2)));
        }
        #pragma unroll
        for (int o = 16; o; o >>= 1) {
            mx = max(mx, __shfl_xor_sync(0xffffffffu, mx, o));
            mw = max(mw, __shfl_xor_sync(0xffffffffu, mw, o));
        }
        if (lane == 0) { sredx[wid] = mx; sredw[wid] = mw; }
        __syncthreads();
        if (t < 32) {
            mx = (t < 16) ? sredx[t] : 0u;
            mw = (t < 16) ? sredw[t] : 0u;
            #pragma unroll
            for (int o = 8; o; o >>= 1) {
                mx = max(mx, __shfl_xor_sync(0xffffffffu, mx, o));
                mw = max(mw, __shfl_xor_sync(0xffffffffu, mw, o));
            }
            if (t == 0) { g_partx[blockIdx.x] = mx; g_partw[blockIdx.x] = mw; }
        }
    }
    grid_bar(&g_barA);

    // ===== phase 2: every CTA finalizes scales locally =====
    {
        unsigned vx = (t < NCTA) ? g_partx[t] : 0u;
        unsigned vw = (t < NCTA) ? g_partw[t] : 0u;
        #pragma unroll
        for (int o = 16; o; o >>= 1) {
            vx = max(vx, __shfl_xor_sync(0xffffffffu, vx, o));
            vw = max(vw, __shfl_xor_sync(0xffffffffu, vw, o));
        }
        if (lane == 0 && t < NCTA) { sredx[wid] = vx; sredw[wid] = vw; }
        __syncthreads();
        if (t == 0) {
            unsigned ax = 0u, aw = 0u;
            #pragma unroll
            for (int i = 0; i < 4; ++i) { ax = max(ax, sredx[i]); aw = max(aw, sredw[i]); }
            float Tf = __fadd_rn(__fmul_rn(0.95f, Tf_in[0]), __fmul_rn(0.05f, __uint_as_float(ax)));
            float Tw = __fadd_rn(__fmul_rn(0.95f, Tw_in[0]), __fmul_rn(0.05f, __uint_as_float(aw)));
            s_sc[0] = __fdiv_rn(127.0f, Tf);
            s_sc[1] = __fdiv_rn(127.0f, Tw);
            s_sc[2] = __fmul_rn(__fdiv_rn(Tf, 127.0f), __fdiv_rn(Tw, 127.0f));
        }
        __syncthreads();
    }

    // ===== phase 3a: quantize halo from SMEM floats into int8 staging =====
    {
        const float sf = s_sc[0];
        #pragma unroll
        for (int k = 0; k < 2; ++k) {
            int i = t + k*NTHR;                // 544 items = 136 pix x 4 c4-groups
            if (i < 544) {
                int pix = i % 136, c4 = i / 136;
                const float* hp = halo + pix*HSTR + c4*16;
                int q[16];
                #pragma unroll
                for (int j = 0; j < 16; ++j)
                    q[j] = quant(hp[j], sf) & 255;
                int4 v;
                v.x = q[0]  | (q[1]  << 8) | (q[2]  << 16) | (q[3]  << 24);
                v.y = q[4]  | (q[5]  << 8) | (q[6]  << 16) | (q[7]  << 24);
                v.z = q[8]  | (q[9]  << 8) | (q[10] << 16) | (q[11] << 24);
                v.w = q[12] | (q[13] << 8) | (q[14] << 16) | (q[15] << 24);
                *(int4*)(sm + STAGE + pix*PIXSTR + c4*16) = v;
            }
        }
    }
    // ===== phase 3b: quantize w row (from smem) to global pack =====
    if (t < 144) {
        const int tap = t >> 4, c4w = t & 15;
        const float sf = s_sc[1];
        int q0 = quant(wrow[(c4w*4 + 0)*9 + tap], sf) & 255;
        int q1 = quant(wrow[(c4w*4 + 1)*9 + tap], sf) & 255;
        int q2 = quant(wrow[(c4w*4 + 2)*9 + tap], sf) & 255;
        int q3 = quant(wrow[(c4w*4 + 3)*9 + tap], sf) & 255;
        g_wpack[blockIdx.x*144 + t] = q0 | (q1 << 8) | (q2 << 16) | (q3 << 24);
    }
    grid_bar(&g_barB);

    // ===== phase 4: fill B smem [co][576B] stride 592 (4608 int4) =====
    {
        const int4* __restrict__ src = (const int4*)g_wpack;
        int4* __restrict__ Bm = (int4*)(sm + BOFF);
        #pragma unroll
        for (int k = 0; k < 9; ++k) {
            int i = t + k*NTHR;
            int co = i / 36, j = i % 36;
            Bm[co*37 + j] = src[i];
        }
    }
    __syncthreads();

    // ===== phase 5: IMMA mainloop; 16 warps = 4(M) x 4(N); warp = m16 x n32 =====
    const int wm = (wid & 3) * 16;
    const int wn = (wid >> 2) * 32;
    const uint32_t sbase = smem_u32(sm);

    // A directly from staging: per-lane pixel base + compile-time tap offsets
    const int pix = wm + (lane & 15);
    const uint32_t aAddr0 = sbase + STAGE
                          + (uint32_t)(((pix >> 5)*34 + (pix & 31))*PIXSTR)
                          + (uint32_t)(lane >> 4)*16;
    uint32_t bAddr[2];
    #pragma unroll
    for (int np = 0; np < 2; ++np)
        bAddr[np] = sbase + BOFF
                  + (uint32_t)(wn + np*16 + (lane & 7) + ((lane >> 4) & 1)*8)*BROW
                  + (uint32_t)((lane >> 3) & 1)*16;

    int acc[4][4];
    #pragma unroll
    for (int nf = 0; nf < 4; ++nf)
        #pragma unroll
        for (int j = 0; j < 4; ++j) acc[nf][j] = 0;

    #pragma unroll
    for (int ks = 0; ks < 18; ++ks) {
        const int tap = ks >> 1;
        const uint32_t aoff = (uint32_t)(((tap/3)*34 + (tap%3))*PIXSTR + (ks & 1)*32);
        const uint32_t boff = (uint32_t)ks * 32;
        uint32_t a[4], bb[2][4];
        LDSM_X4(a[0], a[1], a[2], a[3], aAddr0 + aoff);
        #pragma unroll
        for (int np = 0; np < 2; ++np)
            LDSM_X4(bb[np][0], bb[np][1], bb[np][2], bb[np][3], bAddr[np] + boff);
        #pragma unroll
        for (int nf = 0; nf < 4; ++nf)
            IMMA(acc[nf], a[0], a[1], a[2], a[3],
                 bb[nf >> 1][(nf & 1)*2], bb[nf >> 1][(nf & 1)*2 + 1]);
    }

    // ===== epilogue: s32 -> f32 * sc + bias =====
    const float sc = s_sc[2];
    const int p0 = wm + (lane >> 2);           // pixel for c0/c1 (c2/c3: +8)
    #pragma unroll
    for (int nf = 0; nf < 4; ++nf) {
        const int co0 = wn + nf*8 + (lane & 3)*2;
        const float b0 = __ldg(&bias[co0]);
        const float b1 = __ldg(&bias[co0 + 1]);
        #pragma unroll
        for (int half = 0; half < 2; ++half) {
            const int p = p0 + half*8;
            const int y = y0 + (p >> 5), xx = p & 31;
            float* po = out + (((size_t)b*COUT + co0)*HH + y)*WW + xx;
            po[0]     = (float)acc[nf][half*2]     * sc + b0;
            po[HH*WW] = (float)acc[nf][half*2 + 1] * sc + b1;
        }
    }
}

// ---------------- launch ----------------
extern "C" void kernel_launch(void* const* d_in, const int* in_sizes, int n_in,
                              void* d_out, int out_size) {
    const float* x    = (const float*)d_in[0];
    const float* w    = (const float*)d_in[1];
    const float* bias = (const float*)d_in[2];
    // d_in[3] = lut (exact a*b -> tensor core), d_in[4] = gradient_lut (unused)
    const float* Tf   = (const float*)d_in[5];
    const float* Tw   = (const float*)d_in[6];
    float* out = (float*)d_out;

    cudaFuncSetAttribute(k_fused, cudaFuncAttributeMaxDynamicSharedMemorySize, SMEM_SZ);
    k_fused<<<NCTA, NTHR, SMEM_SZ>>>(x, w, bias, Tf, Tw, out);
}